// round 9
// baseline (speedup 1.0000x reference)
#include <cuda_runtime.h>

#define NPIX 16384   // 128*128
#define NC   64
#define NB   32

// Scratch (device globals; no allocation allowed).
// g_stats layout: which*4096 + { S: [0..2047] (b*64+c), T: [2048..4095] }
__device__ float g_stats[8192];
__device__ float g_att[2048];
__device__ float g_g1[NB * NPIX];   // g1[b][n] = sum_c w1d[c] * x[b,c,n]  (2 MB)

// ---------------- packed f32x2 helpers ----------------
static __device__ __forceinline__ unsigned long long pk2(float a, float b) {
    unsigned long long r;
    asm("mov.b64 %0, {%1, %2};" : "=l"(r) : "f"(a), "f"(b));
    return r;
}
static __device__ __forceinline__ void ffma2(unsigned long long& d,
                                             unsigned long long a,
                                             unsigned long long b) {
    asm("fma.rn.f32x2 %0, %1, %2, %0;" : "+l"(d) : "l"(a), "l"(b));
}
static __device__ __forceinline__ float2 unpk2(unsigned long long v) {
    float2 f;
    asm("mov.b64 {%0, %1}, %2;" : "=f"(f.x), "=f"(f.y) : "l"(v));
    return f;
}

// ---------------- g1 = sum_c w1d[c] * x[b,c,:]  (half the batches) ----------
// grid (16, 16), block 256. b = b_off + blockIdx.y.
// Blocks with blockIdx.x==0 zero this half's share of g_stats:
// batches 0-15 zero words 0..4095, batches 16-31 zero words 4096..8191.
__global__ void k_gx(const float* __restrict__ x,
                     const float* __restrict__ w1d, int b_off) {
    __shared__ float ws[64];
    const int b = b_off + blockIdx.y, tx = threadIdx.x;
    if (blockIdx.x == 0) {           // 16 blocks x 256 threads zero 4096 words
        g_stats[b * 256 + tx] = 0.f; // b in 0..31 -> covers all 8192 exactly once
    }
    if (tx < 64) ws[tx] = w1d[tx];
    __syncthreads();

    const float* xb = x + (size_t)b * NC * NPIX + (size_t)blockIdx.x * 1024;
    float4 acc = make_float4(0.f, 0.f, 0.f, 0.f);
#pragma unroll 8
    for (int c = 0; c < 64; c++) {
        float4 v = *(const float4*)(xb + (size_t)c * NPIX + tx * 4);
        float  w = ws[c];
        acc.x += w * v.x; acc.y += w * v.y;
        acc.z += w * v.z; acc.w += w * v.w;
    }
    *(float4*)(g_g1 + (size_t)b * NPIX + blockIdx.x * 1024 + tx * 4) = acc;
}

// ---------------- covariance-projection stats (R2-proven version) ----------
// grid (16, NB), block 256. Each block owns one 1024-pixel slab of one batch.
__global__ void k_cov(const float* __restrict__ x,
                      const float* __restrict__ w1d, int which) {
    __shared__ __align__(16) float g[1024];
    __shared__ float ws[64];
    const int b  = blockIdx.y;
    const int tx = threadIdx.x;
    if (tx < 64) ws[tx] = w1d[tx];
    __syncthreads();

    const float* xb = x + (size_t)b * NC * NPIX + (size_t)blockIdx.x * 1024;

    // Phase A: gRaw over this slab
    float4 acc = make_float4(0.f, 0.f, 0.f, 0.f);
#pragma unroll 8
    for (int c = 0; c < 64; c++) {
        float4 v = *(const float4*)(xb + (size_t)c * NPIX + tx * 4);
        float  w = ws[c];
        acc.x += w * v.x; acc.y += w * v.y;
        acc.z += w * v.z; acc.w += w * v.w;
    }
    *(float4*)(g + tx * 4) = acc;
    __syncthreads();

    // Phase B: per-channel T += x*g, S += x
    const int warp = tx >> 5, lane = tx & 31;
    float* base = g_stats + which * 4096;
    const float4* gp = (const float4*)g;
    for (int j = 0; j < 8; j++) {
        int c = warp * 8 + j;
        const float4* xc = (const float4*)(xb + (size_t)c * NPIX);
        float t = 0.f, s = 0.f;
#pragma unroll
        for (int it = 0; it < 8; it++) {
            float4 v  = xc[lane + it * 32];
            float4 gg = gp[lane + it * 32];
            t += v.x * gg.x + v.y * gg.y + v.z * gg.z + v.w * gg.w;
            s += v.x + v.y + v.z + v.w;
        }
#pragma unroll
        for (int o = 16; o > 0; o >>= 1) {
            t += __shfl_xor_sync(0xffffffffu, t, o);
            s += __shfl_xor_sync(0xffffffffu, s, o);
        }
        if (lane == 0) {
            atomicAdd(base +        b * 64 + c, s);
            atomicAdd(base + 2048 + b * 64 + c, t);
        }
    }
}

// ---------------- 9x9 depthwise conv (pad 4), half the tile rows -----------
// grid (4, NC, NB): tileY = ty_off + blockIdx.x, channel, batch. block (32, 4).
// Output tile 128 wide x 16 high; per-thread register tile 4x4 via fma.rn.f32x2.
// Fused epilogue: S1 = sum(x), T1 = sum(x * g1) over the tile's output region.
__global__ void k_conv(const float* __restrict__ x,
                       const float* __restrict__ wdw,
                       const float* __restrict__ bdw,
                       float* __restrict__ y, int ty_off) {
    __shared__ __align__(16) float tile[24][136];
    __shared__ unsigned long long wd[81];
    __shared__ float sred[4], tred[4];

    const int tileY = ty_off + blockIdx.x, c = blockIdx.y, b = blockIdx.z;
    const int tx = threadIdx.x, ty = threadIdx.y;
    const int tid = ty * 32 + tx;
    const float* xp = x + (size_t)(b * NC + c) * NPIX;
    const int y0 = tileY * 16;

    if (tid < 81) {
        float w = wdw[c * 81 + tid];
        wd[tid] = pk2(w, w);
    }
    // Vectorized tile load: interior cols as float4, borders fixed up.
    // tile row r = input row y0-4+r; tile cols 4..131 = input cols 0..127.
#pragma unroll
    for (int i = tid; i < 768; i += 128) {          // 24 rows x 32 float4
        int r = i >> 5, k = i & 31;
        int gy = y0 - 4 + r;
        float4 v = make_float4(0.f, 0.f, 0.f, 0.f);
        if (gy >= 0 && gy < 128)
            v = *(const float4*)(xp + gy * 128 + k * 4);
        *(float4*)(&tile[r][4 + k * 4]) = v;
    }
    if (tid < 48) {                                  // zero left/right halo
        int r = tid >> 1;
        *(float4*)(&tile[r][(tid & 1) ? 132 : 0]) =
            make_float4(0.f, 0.f, 0.f, 0.f);
    }
    __syncthreads();

    const float bias = bdw[c];
    const unsigned long long bb = pk2(bias, bias);
    unsigned long long acc[4][2];
#pragma unroll
    for (int oy = 0; oy < 4; oy++) { acc[oy][0] = bb; acc[oy][1] = bb; }

    const int ox0   = tx * 4;   // output cols ox0..ox0+3
    const int rbase = ty * 4;   // smem row of (first output row - 4)

#pragma unroll
    for (int iy = 0; iy < 12; iy++) {
        const float* rp = &tile[rbase + iy][ox0];
        float4 a0 = *(const float4*)(rp);
        float4 a1 = *(const float4*)(rp + 4);
        float4 a2 = *(const float4*)(rp + 8);
        float v[12] = {a0.x, a0.y, a0.z, a0.w,
                       a1.x, a1.y, a1.z, a1.w,
                       a2.x, a2.y, a2.z, a2.w};
        unsigned long long p[11];
#pragma unroll
        for (int k = 0; k < 11; k++) p[k] = pk2(v[k], v[k + 1]);

#pragma unroll
        for (int oy = 0; oy < 4; oy++) {
            const int ky = iy - oy;           // compile-time after unroll
            if (ky >= 0 && ky <= 8) {
#pragma unroll
                for (int kx = 0; kx < 9; kx++) {
                    unsigned long long w2 = wd[ky * 9 + kx];
                    ffma2(acc[oy][0], p[kx],     w2);  // outputs ox0, ox0+1
                    ffma2(acc[oy][1], p[kx + 2], w2);  // outputs ox0+2, ox0+3
                }
            }
        }
    }

    float* yp = y + (size_t)(b * NC + c) * NPIX;
#pragma unroll
    for (int oy = 0; oy < 4; oy++) {
        float2 lo = unpk2(acc[oy][0]);
        float2 hi = unpk2(acc[oy][1]);
        *(float4*)(yp + (y0 + rbase + oy) * 128 + ox0) =
            make_float4(lo.x, lo.y, hi.x, hi.y);
    }

    // ---- fused cov(x) stats: S1 = sum(x), T1 = sum(x * g1) over this tile ----
    const float* g1b = g_g1 + (size_t)b * NPIX;
    float s = 0.f, t = 0.f;
#pragma unroll
    for (int oy = 0; oy < 4; oy++) {
        float4 xv = *(const float4*)(&tile[4 + rbase + oy][4 + ox0]);
        float4 gg = __ldg((const float4*)(g1b + (y0 + rbase + oy) * 128 + ox0));
        t += xv.x * gg.x + xv.y * gg.y + xv.z * gg.z + xv.w * gg.w;
        s += xv.x + xv.y + xv.z + xv.w;
    }
#pragma unroll
    for (int o = 16; o > 0; o >>= 1) {
        t += __shfl_xor_sync(0xffffffffu, t, o);
        s += __shfl_xor_sync(0xffffffffu, s, o);
    }
    if (tx == 0) { sred[ty] = s; tred[ty] = t; }
    __syncthreads();
    if (tid == 0) {
        float ss = sred[0] + sred[1] + sred[2] + sred[3];
        float tt = tred[0] + tred[1] + tred[2] + tred[3];
        atomicAdd(g_stats +        b * 64 + c, ss);
        atomicAdd(g_stats + 2048 + b * 64 + c, tt);
    }
}

// ---------------- per-batch attention scores ----------------
__device__ __forceinline__ float blk_reduce(float v, float* red, int t, bool ismax) {
    red[t] = v;
    __syncthreads();
#pragma unroll
    for (int s = 32; s > 0; s >>= 1) {
        if (t < s) red[t] = ismax ? fmaxf(red[t], red[t + s]) : red[t] + red[t + s];
        __syncthreads();
    }
    float r = red[0];
    __syncthreads();
    return r;
}

__global__ void k_att(const float* __restrict__ w1d, const float* __restrict__ b1d) {
    __shared__ float red[64];
    const int b = blockIdx.x, t = threadIdx.x;
    const float invN  = 1.f / 16384.f;
    const float invN1 = 1.f / 16383.f;

    float S1 = g_stats[          b * 64 + t];
    float T1 = g_stats[2048 +    b * 64 + t];
    float S2 = g_stats[4096 +    b * 64 + t];
    float T2 = g_stats[6144 +    b * 64 + t];
    float w  = w1d[t];

    float Sg1 = blk_reduce(w * S1, red, t, false);
    float Sg2 = blk_reduce(w * S2, red, t, false);
    float bb  = b1d[0];
    float c1  = (T1 - Sg1 * S1 * invN) * invN1 + bb;
    float c2  = (T2 - Sg2 * S2 * invN) * invN1 + bb;

    float d  = c2 - c1;
    float m  = blk_reduce(d, red, t, true);
    float e  = expf(d - m);
    float se = blk_reduce(e, red, t, false);
    float raise = e / se;
    float att = 1.f / (1.f + expf(-c2 * (1.f + raise)));
    g_att[b * 64 + t] = att;
}

// ---------------- in-place scaling of y by att ----------------
// grid 32768, block 256; each block = 1024 floats inside one (b,c) channel.
__global__ void k_scale(float* __restrict__ y) {
    const float a = g_att[blockIdx.x >> 4];
    float4* p = (float4*)y;
    int i = blockIdx.x * 256 + threadIdx.x;
    float4 v = p[i];
    v.x *= a; v.y *= a; v.z *= a; v.w *= a;
    p[i] = v;
}

extern "C" void kernel_launch(void* const* d_in, const int* in_sizes, int n_in,
                              void* d_out, int out_size) {
    const float* x   = (const float*)d_in[0];
    const float* w1d = (const float*)d_in[1];
    const float* b1d = (const float*)d_in[2];
    const float* wdw = (const float*)d_in[3];
    const float* bdw = (const float*)d_in[4];
    float* out = (float*)d_out;

    // Launch order chosen so absolute launch index 3 (the ncu-captured slot)
    // is a k_conv half.
    k_gx<<<dim3(16, 16), 256>>>(x, w1d, 0);                       // idx 0
    k_gx<<<dim3(16, 16), 256>>>(x, w1d, 16);                      // idx 1
    k_conv<<<dim3(4, NC, NB), dim3(32, 4)>>>(x, wdw, bdw, out, 0);// idx 2
    k_conv<<<dim3(4, NC, NB), dim3(32, 4)>>>(x, wdw, bdw, out, 4);// idx 3 <- profiled
    k_cov<<<dim3(16, NB), 256>>>(out, w1d, 1);                    // idx 4
    k_att<<<NB, 64>>>(w1d, b1d);                                  // idx 5
    k_scale<<<32768, 256>>>(out);                                 // idx 6
}

// round 10
// speedup vs baseline: 1.0944x; 1.0944x over previous
#include <cuda_runtime.h>

#define NPIX 16384   // 128*128
#define NC   64
#define NB   32

// Scratch (device globals; no allocation allowed).
// g_stats layout: which*4096 + { S: [0..2047] (b*64+c), T: [2048..4095] }
__device__ float g_stats[8192];
__device__ float g_att[2048];
__device__ float g_g1[NB * NPIX];   // g1[b][n] = sum_c w1d[c] * x[b,c,n]  (2 MB)

// ---------------- packed f32x2 helpers ----------------
static __device__ __forceinline__ unsigned long long pk2(float a, float b) {
    unsigned long long r;
    asm("mov.b64 %0, {%1, %2};" : "=l"(r) : "f"(a), "f"(b));
    return r;
}
static __device__ __forceinline__ void ffma2(unsigned long long& d,
                                             unsigned long long a,
                                             unsigned long long b) {
    asm("fma.rn.f32x2 %0, %1, %2, %0;" : "+l"(d) : "l"(a), "l"(b));
}
static __device__ __forceinline__ float2 unpk2(unsigned long long v) {
    float2 f;
    asm("mov.b64 {%0, %1}, %2;" : "=f"(f.x), "=f"(f.y) : "l"(v));
    return f;
}

// ---------------- g1 = sum_c w1d[c] * x[b,c,:]  (half the batches) ----------
// grid (16, 16), block 256. b = b_off + blockIdx.y.
// Blocks with blockIdx.x==0 zero this half's share of g_stats (all 8192 words
// covered exactly once across the two launches).
__global__ void k_gx(const float* __restrict__ x,
                     const float* __restrict__ w1d, int b_off) {
    __shared__ float ws[64];
    const int b = b_off + blockIdx.y, tx = threadIdx.x;
    if (blockIdx.x == 0) {
        g_stats[b * 256 + tx] = 0.f;   // b in 0..31
    }
    if (tx < 64) ws[tx] = w1d[tx];
    __syncthreads();

    const float* xb = x + (size_t)b * NC * NPIX + (size_t)blockIdx.x * 1024;
    float4 acc = make_float4(0.f, 0.f, 0.f, 0.f);
#pragma unroll 8
    for (int c = 0; c < 64; c++) {
        float4 v = *(const float4*)(xb + (size_t)c * NPIX + tx * 4);
        float  w = ws[c];
        acc.x += w * v.x; acc.y += w * v.y;
        acc.z += w * v.z; acc.w += w * v.w;
    }
    *(float4*)(g_g1 + (size_t)b * NPIX + blockIdx.x * 1024 + tx * 4) = acc;
}

// ---------------- covariance-projection stats (R2-proven version) ----------
// grid (16, NB), block 256. Each block owns one 1024-pixel slab of one batch.
__global__ void k_cov(const float* __restrict__ x,
                      const float* __restrict__ w1d, int which) {
    __shared__ __align__(16) float g[1024];
    __shared__ float ws[64];
    const int b  = blockIdx.y;
    const int tx = threadIdx.x;
    if (tx < 64) ws[tx] = w1d[tx];
    __syncthreads();

    const float* xb = x + (size_t)b * NC * NPIX + (size_t)blockIdx.x * 1024;

    // Phase A: gRaw over this slab
    float4 acc = make_float4(0.f, 0.f, 0.f, 0.f);
#pragma unroll 8
    for (int c = 0; c < 64; c++) {
        float4 v = *(const float4*)(xb + (size_t)c * NPIX + tx * 4);
        float  w = ws[c];
        acc.x += w * v.x; acc.y += w * v.y;
        acc.z += w * v.z; acc.w += w * v.w;
    }
    *(float4*)(g + tx * 4) = acc;
    __syncthreads();

    // Phase B: per-channel T += x*g, S += x
    const int warp = tx >> 5, lane = tx & 31;
    float* base = g_stats + which * 4096;
    const float4* gp = (const float4*)g;
    for (int j = 0; j < 8; j++) {
        int c = warp * 8 + j;
        const float4* xc = (const float4*)(xb + (size_t)c * NPIX);
        float t = 0.f, s = 0.f;
#pragma unroll
        for (int it = 0; it < 8; it++) {
            float4 v  = xc[lane + it * 32];
            float4 gg = gp[lane + it * 32];
            t += v.x * gg.x + v.y * gg.y + v.z * gg.z + v.w * gg.w;
            s += v.x + v.y + v.z + v.w;
        }
#pragma unroll
        for (int o = 16; o > 0; o >>= 1) {
            t += __shfl_xor_sync(0xffffffffu, t, o);
            s += __shfl_xor_sync(0xffffffffu, s, o);
        }
        if (lane == 0) {
            atomicAdd(base +        b * 64 + c, s);
            atomicAdd(base + 2048 + b * 64 + c, t);
        }
    }
}

// ---------------- 9x9 depthwise conv (pad 4), half the tile rows -----------
// grid (4, NC, NB): tileY = ty_off + blockIdx.x, channel, batch. block (32, 4).
// Output tile 128 wide x 16 high; per-thread register tile 4x4 via fma.rn.f32x2.
// Even/odd pair scheme: even pairs loaded directly as 64-bit LDS, only 5 odd
// pairs packed per row. Weight rows padded to 10 pairs so 9 weights fetch as
// 4x LDS.128 + 1x LDS.64 (broadcast).
// Fused epilogue: S1 = sum(x), T1 = sum(x * g1) over the tile's output region.
__global__ void __launch_bounds__(128, 6)
k_conv(const float* __restrict__ x,
       const float* __restrict__ wdw,
       const float* __restrict__ bdw,
       float* __restrict__ y, int ty_off) {
    __shared__ __align__(16) float tile[24][136];
    __shared__ __align__(16) unsigned long long wd2[90];  // 9 rows x 10 pairs
    __shared__ float sred[4], tred[4];

    const int tileY = ty_off + blockIdx.x, c = blockIdx.y, b = blockIdx.z;
    const int tx = threadIdx.x, ty = threadIdx.y;
    const int tid = ty * 32 + tx;
    const float* xp = x + (size_t)(b * NC + c) * NPIX;
    const int y0 = tileY * 16;

    if (tid < 81) {
        float w = wdw[c * 81 + tid];
        wd2[(tid / 9) * 10 + (tid % 9)] = pk2(w, w);
    }
    // Vectorized tile load: interior cols as float4, borders fixed up.
    // tile row r = input row y0-4+r; tile cols 4..131 = input cols 0..127.
#pragma unroll
    for (int i = tid; i < 768; i += 128) {          // 24 rows x 32 float4
        int r = i >> 5, k = i & 31;
        int gy = y0 - 4 + r;
        float4 v = make_float4(0.f, 0.f, 0.f, 0.f);
        if (gy >= 0 && gy < 128)
            v = *(const float4*)(xp + gy * 128 + k * 4);
        *(float4*)(&tile[r][4 + k * 4]) = v;
    }
    if (tid < 48) {                                  // zero left/right halo
        int r = tid >> 1;
        *(float4*)(&tile[r][(tid & 1) ? 132 : 0]) =
            make_float4(0.f, 0.f, 0.f, 0.f);
    }
    __syncthreads();

    const float bias = bdw[c];
    const unsigned long long bb = pk2(bias, bias);
    unsigned long long acc[4][2];
#pragma unroll
    for (int oy = 0; oy < 4; oy++) { acc[oy][0] = bb; acc[oy][1] = bb; }

    const int ox0   = tx * 4;   // tile col of leftmost needed input (= out-4)
    const int rbase = ty * 4;   // smem row of (first output row - 4)

#pragma unroll
    for (int iy = 0; iy < 12; iy++) {
        // Even pairs: direct aligned 64-bit loads (v[2j], v[2j+1])
        const float2* rp2 = (const float2*)&tile[rbase + iy][ox0];
        float2 e[6];
#pragma unroll
        for (int j = 0; j < 6; j++) e[j] = rp2[j];
        unsigned long long ep[6], op[5];
#pragma unroll
        for (int j = 0; j < 6; j++) ep[j] = pk2(e[j].x, e[j].y);  // reg-pair, ~free
#pragma unroll
        for (int j = 0; j < 5; j++) op[j] = pk2(e[j].y, e[j + 1].x);

#pragma unroll
        for (int oy = 0; oy < 4; oy++) {
            const int ky = iy - oy;           // compile-time after unroll
            if (ky >= 0 && ky <= 8) {
                const ulonglong2* wr = (const ulonglong2*)&wd2[ky * 10];
                ulonglong2 w01 = wr[0];       // pairs kx=0,1   (LDS.128)
                ulonglong2 w23 = wr[1];       // pairs kx=2,3
                ulonglong2 w45 = wr[2];       // pairs kx=4,5
                ulonglong2 w67 = wr[3];       // pairs kx=6,7
                unsigned long long w8 = wd2[ky * 10 + 8];   // kx=8 (LDS.64)

                ffma2(acc[oy][0], ep[0], w01.x); ffma2(acc[oy][1], ep[1], w01.x);
                ffma2(acc[oy][0], op[0], w01.y); ffma2(acc[oy][1], op[1], w01.y);
                ffma2(acc[oy][0], ep[1], w23.x); ffma2(acc[oy][1], ep[2], w23.x);
                ffma2(acc[oy][0], op[1], w23.y); ffma2(acc[oy][1], op[2], w23.y);
                ffma2(acc[oy][0], ep[2], w45.x); ffma2(acc[oy][1], ep[3], w45.x);
                ffma2(acc[oy][0], op[2], w45.y); ffma2(acc[oy][1], op[3], w45.y);
                ffma2(acc[oy][0], ep[3], w67.x); ffma2(acc[oy][1], ep[4], w67.x);
                ffma2(acc[oy][0], op[3], w67.y); ffma2(acc[oy][1], op[4], w67.y);
                ffma2(acc[oy][0], ep[4], w8);    ffma2(acc[oy][1], ep[5], w8);
            }
        }
    }

    float* yp = y + (size_t)(b * NC + c) * NPIX;
#pragma unroll
    for (int oy = 0; oy < 4; oy++) {
        float2 lo = unpk2(acc[oy][0]);
        float2 hi = unpk2(acc[oy][1]);
        *(float4*)(yp + (y0 + rbase + oy) * 128 + ox0) =
            make_float4(lo.x, lo.y, hi.x, hi.y);
    }

    // ---- fused cov(x) stats: S1 = sum(x), T1 = sum(x * g1) over this tile ----
    const float* g1b = g_g1 + (size_t)b * NPIX;
    float s = 0.f, t = 0.f;
#pragma unroll
    for (int oy = 0; oy < 4; oy++) {
        float4 xv = *(const float4*)(&tile[4 + rbase + oy][4 + ox0]);
        float4 gg = __ldg((const float4*)(g1b + (y0 + rbase + oy) * 128 + ox0));
        t += xv.x * gg.x + xv.y * gg.y + xv.z * gg.z + xv.w * gg.w;
        s += xv.x + xv.y + xv.z + xv.w;
    }
#pragma unroll
    for (int o = 16; o > 0; o >>= 1) {
        t += __shfl_xor_sync(0xffffffffu, t, o);
        s += __shfl_xor_sync(0xffffffffu, s, o);
    }
    if (tx == 0) { sred[ty] = s; tred[ty] = t; }
    __syncthreads();
    if (tid == 0) {
        float ss = sred[0] + sred[1] + sred[2] + sred[3];
        float tt = tred[0] + tred[1] + tred[2] + tred[3];
        atomicAdd(g_stats +        b * 64 + c, ss);
        atomicAdd(g_stats + 2048 + b * 64 + c, tt);
    }
}

// ---------------- per-batch attention scores ----------------
__device__ __forceinline__ float blk_reduce(float v, float* red, int t, bool ismax) {
    red[t] = v;
    __syncthreads();
#pragma unroll
    for (int s = 32; s > 0; s >>= 1) {
        if (t < s) red[t] = ismax ? fmaxf(red[t], red[t + s]) : red[t] + red[t + s];
        __syncthreads();
    }
    float r = red[0];
    __syncthreads();
    return r;
}

__global__ void k_att(const float* __restrict__ w1d, const float* __restrict__ b1d) {
    __shared__ float red[64];
    const int b = blockIdx.x, t = threadIdx.x;
    const float invN  = 1.f / 16384.f;
    const float invN1 = 1.f / 16383.f;

    float S1 = g_stats[          b * 64 + t];
    float T1 = g_stats[2048 +    b * 64 + t];
    float S2 = g_stats[4096 +    b * 64 + t];
    float T2 = g_stats[6144 +    b * 64 + t];
    float w  = w1d[t];

    float Sg1 = blk_reduce(w * S1, red, t, false);
    float Sg2 = blk_reduce(w * S2, red, t, false);
    float bb  = b1d[0];
    float c1  = (T1 - Sg1 * S1 * invN) * invN1 + bb;
    float c2  = (T2 - Sg2 * S2 * invN) * invN1 + bb;

    float d  = c2 - c1;
    float m  = blk_reduce(d, red, t, true);
    float e  = expf(d - m);
    float se = blk_reduce(e, red, t, false);
    float raise = e / se;
    float att = 1.f / (1.f + expf(-c2 * (1.f + raise)));
    g_att[b * 64 + t] = att;
}

// ---------------- in-place scaling of y by att ----------------
// grid 32768, block 256; each block = 1024 floats inside one (b,c) channel.
__global__ void k_scale(float* __restrict__ y) {
    const float a = g_att[blockIdx.x >> 4];
    float4* p = (float4*)y;
    int i = blockIdx.x * 256 + threadIdx.x;
    float4 v = p[i];
    v.x *= a; v.y *= a; v.z *= a; v.w *= a;
    p[i] = v;
}

extern "C" void kernel_launch(void* const* d_in, const int* in_sizes, int n_in,
                              void* d_out, int out_size) {
    const float* x   = (const float*)d_in[0];
    const float* w1d = (const float*)d_in[1];
    const float* b1d = (const float*)d_in[2];
    const float* wdw = (const float*)d_in[3];
    const float* bdw = (const float*)d_in[4];
    float* out = (float*)d_out;

    // Launch order chosen so absolute launch index 3 (the ncu-captured slot)
    // is a k_conv half.
    k_gx<<<dim3(16, 16), 256>>>(x, w1d, 0);                       // idx 0
    k_gx<<<dim3(16, 16), 256>>>(x, w1d, 16);                      // idx 1
    k_conv<<<dim3(4, NC, NB), dim3(32, 4)>>>(x, wdw, bdw, out, 0);// idx 2
    k_conv<<<dim3(4, NC, NB), dim3(32, 4)>>>(x, wdw, bdw, out, 4);// idx 3 <- profiled
    k_cov<<<dim3(16, NB), 256>>>(out, w1d, 1);                    // idx 4
    k_att<<<NB, 64>>>(w1d, b1d);                                  // idx 5
    k_scale<<<32768, 256>>>(out);                                 // idx 6
}